// round 6
// baseline (speedup 1.0000x reference)
#include <cuda_runtime.h>
#include <math_constants.h>

#define BB 4096
#define PP 128
#define GG 128

#define SCX (8000.0f / 79.0f)
#define SCY (8000.0f / 79.0f)
#define SCZ (2000.0f / 19.0f)
#define BX (-4000.0f)
#define BY (-4000.0f)
#define BZ (0.0f)

#define DIST_THRESH_SQ (500.0f * 500.0f)
#define BBOX_THRESH 0.1f
#define EOFF 2.0e8f              // offset making e strictly positive
#define KEYMASK (~31)            // drop low 5 float bits, store q (q < 32)

// ---- packed f32x2 helpers (sm_103a) ----
__device__ __forceinline__ unsigned long long pack2(float lo, float hi) {
    unsigned long long r;
    asm("mov.b64 %0, {%1, %2};" : "=l"(r) : "f"(lo), "f"(hi));
    return r;
}
__device__ __forceinline__ void unpack2(unsigned long long v, float& lo, float& hi) {
    asm("mov.b64 {%0, %1}, %2;" : "=f"(lo), "=f"(hi) : "l"(v));
}
__device__ __forceinline__ unsigned long long fma2(unsigned long long a, unsigned long long b,
                                                   unsigned long long c) {
    unsigned long long r;
    asm("fma.rn.f32x2 %0, %1, %2, %3;" : "=l"(r) : "l"(a), "l"(b), "l"(c));
    return r;
}

__global__ __launch_bounds__(256, 8)
void proposal_layer_kernel(const int*   __restrict__ topk_index,      // [B,P,3]
                           const float* __restrict__ topk_confs,      // [B,P]
                           const float* __restrict__ match_bbox_preds,// [B,P,2]
                           const float* __restrict__ roots_3d,        // [B,G,3]
                           const float* __restrict__ gt_bbox,         // [B,G,2]
                           const int*   __restrict__ num_person,      // [B]
                           float*       __restrict__ out)             // [B,P,7]
{
    const int b    = blockIdx.x;
    const int tid  = threadIdx.x;      // 0..255
    const int p    = tid & 127;        // proposal id
    const int half = tid >> 7;         // team 0 scans low chunks, team 1 high+tail

    __shared__ __align__(16) float s_nx[GG];   // -rx
    __shared__ __align__(16) float s_ny[GG];   // -ry
    __shared__ __align__(16) float s_nz[GG];   // -rz
    __shared__ __align__(16) float s_h [GG];   // |r|^2/2 + EOFF
    __shared__ float2 s_bbox[GG];
    __shared__ int2   s_part[2][PP];           // per-team {masked key, index}
    __shared__ float  s_out[PP * 7];

    // staging: team 0 writes coord arrays, team 1 writes bbox (one g each)
    if (half == 0) {
        const float* r = roots_3d + ((size_t)b * GG + p) * 3;
        float rx = r[0], ry = r[1], rz = r[2];
        s_nx[p] = -rx;
        s_ny[p] = -ry;
        s_nz[p] = -rz;
        s_h [p] = __fmaf_rn(0.5f, __fmaf_rn(rz, rz, __fmaf_rn(ry, ry, rx * rx)), EOFF);
    } else {
        const float* gb = gt_bbox + ((size_t)b * GG + p) * 2;
        s_bbox[p] = make_float2(gb[0], gb[1]);
    }
    const int n = num_person[b];
    __syncthreads();

    // proposal coords (both teams compute identically; loads hit L1 second time)
    const int* ti = topk_index + ((size_t)b * PP + p) * 3;
    const float cx = (float)ti[0] * SCX + BX;
    const float cy = (float)ti[1] * SCY + BY;
    const float cz = (float)ti[2] * SCZ + BZ;

    const unsigned long long cxx = pack2(cx, cx);
    const unsigned long long cyy = pack2(cy, cy);
    const unsigned long long czz = pack2(cz, cz);

    const ulonglong2* px = (const ulonglong2*)s_nx;
    const ulonglong2* py = (const ulonglong2*)s_ny;
    const ulonglong2* pz = (const ulonglong2*)s_nz;
    const ulonglong2* ph = (const ulonglong2*)s_h;

    // chunk range for this team: [q0, q1)
    const int nb  = n >> 2;
    const int nb2 = (nb + 1) >> 1;
    const int qlo = half ? nb2 : 0;
    const int qhi = half ? nb  : nb2;

    int bk0 = 0x7FFFFFFF, bk1 = 0x7FFFFFFF, bk2 = 0x7FFFFFFF, bk3 = 0x7FFFFFFF;

    #pragma unroll 2
    for (int q = qlo; q < qhi; ++q) {
        ulonglong2 X = px[q];   // LDS.128 broadcast
        ulonglong2 Y = py[q];
        ulonglong2 Z = pz[q];
        ulonglong2 H = ph[q];

        unsigned long long eA = fma2(cxx, X.x, fma2(cyy, Y.x, fma2(czz, Z.x, H.x)));
        unsigned long long eB = fma2(cxx, X.y, fma2(cyy, Y.y, fma2(czz, Z.y, H.y)));
        float s0, s1, s2, s3;
        unpack2(eA, s0, s1);
        unpack2(eB, s2, s3);

        bk0 = min(bk0, (__float_as_int(s0) & KEYMASK) | q);
        bk1 = min(bk1, (__float_as_int(s1) & KEYMASK) | q);
        bk2 = min(bk2, (__float_as_int(s2) & KEYMASK) | q);
        bk3 = min(bk3, (__float_as_int(s3) & KEYMASK) | q);
    }

    // merge 4 residue chains (masked value, strict <; residue order = g order)
    int best_mv = bk0 & KEYMASK;
    int bi = ((bk0 & 31) << 2);
    { int mv = bk1 & KEYMASK; if (mv < best_mv) { best_mv = mv; bi = ((bk1 & 31) << 2) + 1; } }
    { int mv = bk2 & KEYMASK; if (mv < best_mv) { best_mv = mv; bi = ((bk2 & 31) << 2) + 2; } }
    { int mv = bk3 & KEYMASK; if (mv < best_mv) { best_mv = mv; bi = ((bk3 & 31) << 2) + 3; } }

    // team 1 also handles the scalar tail g in [nb*4, n)
    if (half) {
        for (int g = (nb << 2); g < n; ++g) {
            float e = __fmaf_rn(cx, s_nx[g],
                     __fmaf_rn(cy, s_ny[g],
                     __fmaf_rn(cz, s_nz[g], s_h[g])));
            int mv = __float_as_int(e) & KEYMASK;
            if (mv < best_mv) { best_mv = mv; bi = g; }
        }
    }

    s_part[half][p] = make_int2(best_mv, bi);
    __syncthreads();

    // team 0 finalizes proposal p
    if (half == 0) {
        int2 p0 = s_part[0][p];
        int2 p1 = s_part[1][p];
        // team 0 covers lower g: strict < keeps first minimum
        int fbi = (p1.x < p0.x) ? p1.y : p0.y;

        const float cc = __fmaf_rn(cz, cz, __fmaf_rn(cy, cy, cx * cx));
        // exact threshold recheck: d2 <= 500^2  <=>  e+EOFF <= 0.5*(500^2-cc)+EOFF
        const float e_best = __fmaf_rn(cx, s_nx[fbi],
                            __fmaf_rn(cy, s_ny[fbi],
                            __fmaf_rn(cz, s_nz[fbi], s_h[fbi])));
        const float thresh_e = __fmaf_rn(-0.5f, cc, 0.5f * DIST_THRESH_SQ + EOFF);
        const bool matched = !(e_best > thresh_e);
        const float p2g = matched ? (float)fbi : -1.0f;

        const float conf = topk_confs[(size_t)b * PP + p];
        const float* mp = match_bbox_preds + ((size_t)b * PP + p) * 2;
        const float pb0 = mp[0];
        const float pb1 = mp[1];

        float2 mb = s_bbox[fbi];
        bool ow = matched && ((pb0 < mb.x - BBOX_THRESH) || (pb1 < mb.y - BBOX_THRESH));
        const float o5 = ow ? mb.x : pb0;
        const float o6 = ow ? mb.y : pb1;

        float* so = s_out + p * 7;  // stride 7 -> conflict-free
        so[0] = cx; so[1] = cy; so[2] = cz;
        so[3] = p2g; so[4] = conf;
        so[5] = o5;  so[6] = o6;
    }
    __syncthreads();

    // coalesced store of 896 floats by 256 threads
    float* ob = out + (size_t)b * (PP * 7);
    #pragma unroll
    for (int i = tid; i < PP * 7; i += 256)
        ob[i] = s_out[i];
}

extern "C" void kernel_launch(void* const* d_in, const int* in_sizes, int n_in,
                              void* d_out, int out_size)
{
    const int*   topk_index       = (const int*)  d_in[0];
    const float* topk_confs       = (const float*)d_in[1];
    const float* match_bbox_preds = (const float*)d_in[2];
    const float* roots_3d         = (const float*)d_in[3];
    const float* gt_bbox          = (const float*)d_in[4];
    const int*   num_person       = (const int*)  d_in[5];
    float* out = (float*)d_out;

    proposal_layer_kernel<<<BB, 256>>>(topk_index, topk_confs, match_bbox_preds,
                                       roots_3d, gt_bbox, num_person, out);
}